// round 9
// baseline (speedup 1.0000x reference)
#include <cuda_runtime.h>
#include <cuda_fp16.h>

// MVF_Dyn: trilinear-upsampled motion-field warp of a 2-channel 3D image.
//   image:       [1,1,48,256,256,2] f32
//   mvf_kernels: [1,4,3,48,128,128] f32
//   out:         [1,5,48,256,256,2] f32  (phase 0 = copy of image, 1..4 warped)
//
// Round-8 resubmit (infra flake): r7 warp kernel (2 rows/block, 256 thr,
// predicated OOB; L1-bound at 84.8%) kept intact with 32-bit output indexing;
// prep kernel vectorized (float4 loads, paired uint4 + float4 stores, half
// the ld/st instructions).

namespace {

constexpr int Dv = 48, Hv = 256, Wv = 256;
constexpr int HM = 128, WM = 128;
constexpr int PH = 4;

// 48*256*256 * 16B = 50.3 MB scratch (z+x paired fp16).
__device__ uint4 g_pairs[Dv * Hv * Wv];

__device__ __forceinline__ unsigned pack_h2(float a, float b) {
  __half2 h = __floats2half2_rn(a, b);
  return *reinterpret_cast<unsigned*>(&h);
}

// Builds g_pairs (fp16, z+x paired) and writes the phase-0 fp32 copy.
// Block = one (z,y) row; 128 threads, thread t owns pixels x = 2t, 2t+1.
__global__ void __launch_bounds__(128)
prep_kernel(const float4* __restrict__ img4, float4* __restrict__ out04) {
  const int y = blockIdx.x & (Hv - 1);
  const int z = blockIdx.x >> 8;       // Hv = 256
  const int t = threadIdx.x;           // 0..127 -> x-pair
  __shared__ float4 srow[2][WM + 1];   // [zrow][x-pair], +1 zero pad

  const int rbase4 = (z * Hv + y) * (Wv / 2);   // float4 units (2 px each)
  const float4 v0 = img4[rbase4 + t];           // px (2t, 2t+1) @ z
  float4 v1 = make_float4(0.f, 0.f, 0.f, 0.f);
  if (z + 1 < Dv) v1 = img4[rbase4 + Hv * (Wv / 2) + t];
  srow[0][t] = v0;
  srow[1][t] = v1;
  if (t == 0) {
    srow[0][WM] = make_float4(0.f, 0.f, 0.f, 0.f);
    srow[1][WM] = make_float4(0.f, 0.f, 0.f, 0.f);
  }
  __syncthreads();
  const float4 n0 = srow[0][t + 1];    // px (2t+2, 2t+3) @ z
  const float4 n1 = srow[1][t + 1];

  // Entry for x=2t:   (z,2t)(z,2t+1)(z+1,2t)(z+1,2t+1)
  uint4 qa;
  qa.x = pack_h2(v0.x, v0.y);
  qa.y = pack_h2(v0.z, v0.w);
  qa.z = pack_h2(v1.x, v1.y);
  qa.w = pack_h2(v1.z, v1.w);
  // Entry for x=2t+1: (z,2t+1)(z,2t+2)(z+1,2t+1)(z+1,2t+2)
  uint4 qb;
  qb.x = qa.y;
  qb.y = pack_h2(n0.x, n0.y);
  qb.z = qa.w;
  qb.w = pack_h2(n1.x, n1.y);

  const int ebase = (z * Hv + y) * Wv + 2 * t;
  g_pairs[ebase] = qa;
  g_pairs[ebase + 1] = qb;
  out04[rbase4 + t] = v0;              // phase-0 copy (exact fp32)
}

__device__ __forceinline__ float2 h2f(unsigned u) {
  return __half22float2(*reinterpret_cast<__half2*>(&u));
}

// Trilinear sample with zero padding; z+x paired fp16 layout; fp32 math.
// Early-out on fully-OOB x/z (rare), predicated y taps.
__device__ __forceinline__ float2 sample_one(float z, float y, float x) {
  const int z0 = __float2int_rd(z);
  const int y0 = __float2int_rd(y);
  const int x0 = __float2int_rd(x);
  const float wz = z - (float)z0, wy = y - (float)y0, wx = x - (float)x0;

  const bool xin = (unsigned)x0 < (unsigned)Wv;
  if (!xin && x0 != -1) return make_float2(0.f, 0.f);
  const int xc = xin ? x0 : 0;
  const float wa = xin ? (1.f - wx) : wx;   // x0 half (x0==-1: tap x=0 w/ wx)
  const float wb = xin ? wx : 0.f;          // x0+1 half

  const bool zin = (unsigned)z0 < (unsigned)Dv;
  if (!zin && z0 != -1) return make_float2(0.f, 0.f);
  const int zc = zin ? z0 : 0;
  const float za = zin ? (1.f - wz) : wz;   // z lo half
  const float zb = zin ? wz : 0.f;          // z hi half

  const int base = zc * (Hv * Wv) + xc;     // 32-bit index
  float ax = 0.f, ay = 0.f;
#pragma unroll
  for (int dy = 0; dy < 2; dy++) {
    const int yi = y0 + dy;
    if ((unsigned)yi >= (unsigned)Hv) continue;
    const float wyy = dy ? wy : 1.f - wy;
    const uint4 q = __ldg(&g_pairs[base + yi * Wv]);
    const float2 a0 = h2f(q.x);  // (z0,   x0)
    const float2 a1 = h2f(q.y);  // (z0,   x1)
    const float2 b0 = h2f(q.z);  // (z0+1, x0)
    const float2 b1 = h2f(q.w);  // (z0+1, x1)
    const float t0x = fmaf(za, a0.x, zb * b0.x), t0y = fmaf(za, a0.y, zb * b0.y);
    const float t1x = fmaf(za, a1.x, zb * b1.x), t1y = fmaf(za, a1.y, zb * b1.y);
    ax = fmaf(wyy, fmaf(wa, t0x, wb * t1x), ax);
    ay = fmaf(wyy, fmaf(wa, t0y, wb * t1y), ay);
  }
  return make_float2(ax, ay);
}

// Block: 256 threads = 2 output rows (h0, h0+1) of one (d, p).
// Thread: r = tid>>7 (row), k = tid&127 (w-pair) -> 2 samples, 4 LDG.128s.
// jax.image.resize 'trilinear' 2x (half-pixel, edge-renormalized):
//   even out idx 2j   -> taps (j-1, j)  weights (0.25, 0.75), clamp at edges
//   odd  out idx 2j+1 -> taps (j, j+1)  weights (0.75, 0.25), clamp at edges
// Depth is identity.
__global__ void __launch_bounds__(256)
warp_kernel(const float* __restrict__ mvf,    // [4][3][48][128][128]
            float4* __restrict__ out) {       // output as float4 (w pairs)
  const int h0 = blockIdx.x * 2;
  const int d = blockIdx.y;
  const int p = blockIdx.z;
  const int tid = threadIdx.x;
  const int k = tid & (WM - 1);   // 0..127 w-pair
  const int r = tid >> 7;         // 0..1 output row
  const int a = h0 >> 1;

  // Stage mvf source rows a-1, a, a+1 (clamped) for 3 channels.
  __shared__ float s[3][3][WM];
  if (tid < WM) {
    const int r0 = max(a - 1, 0), r1 = a, r2 = min(a + 1, HM - 1);
    const float* pl = mvf + ((size_t)(p * 3) * Dv + d) * (size_t)(HM * WM);
    const int plane = Dv * HM * WM;
#pragma unroll
    for (int c = 0; c < 3; c++) {
      const float* pc = pl + c * plane;
      s[c][0][tid] = __ldg(pc + r0 * WM + tid);
      s[c][1][tid] = __ldg(pc + r1 * WM + tid);
      s[c][2][tid] = __ldg(pc + r2 * WM + tid);
    }
  }
  __syncthreads();

  const int km1 = max(k - 1, 0);
  const int kp1 = min(k + 1, WM - 1);

  // Row r: even row h0 uses y-taps (row0,row1) w/ (0.25,0.75);
  //        odd row h0+1 uses (row1,row2) w/ (0.75,0.25).
  const int ra = r ? 1 : 0, rb = r ? 2 : 1;
  const float tya = r ? 0.75f : 0.25f, tyb = r ? 0.25f : 0.75f;

  float me[3], mo[3];  // upsampled mvf at w=2k (even) and 2k+1 (odd)
#pragma unroll
  for (int c = 0; c < 3; c++) {
    const float aA = s[c][ra][km1], bA = s[c][ra][k], cA = s[c][ra][kp1];
    const float aB = s[c][rb][km1], bB = s[c][rb][k], cB = s[c][rb][kp1];
    const float eA = fmaf(0.25f, aA, 0.75f * bA), oA = fmaf(0.75f, bA, 0.25f * cA);
    const float eB = fmaf(0.25f, aB, 0.75f * bB), oB = fmaf(0.75f, bB, 0.25f * cB);
    me[c] = fmaf(tya, eA, tyb * eB);
    mo[c] = fmaf(tya, oA, tyb * oB);
  }

  const float fd = (float)d;
  const float fh = (float)(h0 + r);
  const float xe = (float)(2 * k), xo = (float)(2 * k + 1);

  const float2 re = sample_one(fd + me[0], fh + 2.f * me[1], xe + 2.f * me[2]);
  const float2 ro = sample_one(fd + mo[0], fh + 2.f * mo[1], xo + 2.f * mo[2]);

  // 32-bit output index: max (5*48*256)*128 = 7.9M < 2^31.
  const int oidx = (((p + 1) * Dv + d) * Hv + (h0 + r)) * (Wv / 2) + k;
  out[oidx] = make_float4(re.x, re.y, ro.x, ro.y);
}

}  // namespace

extern "C" void kernel_launch(void* const* d_in, const int* in_sizes, int n_in,
                              void* d_out, int out_size) {
  const float* image = (const float*)d_in[0];
  const float* mvf   = (const float*)d_in[1];
  // Defensive: identify inputs by size (image has 48*256*256*2 = 6291456 elems).
  if (n_in >= 2 && in_sizes[0] != Dv * Hv * Wv * 2) {
    const float* t = image; image = mvf; mvf = t;
  }

  // Build z+x paired fp16 layout + phase-0 copy (vectorized).
  prep_kernel<<<Dv * Hv, 128>>>((const float4*)image, (float4*)d_out);

  // Phases 1..4: warp. 2 output rows per 256-thread block.
  dim3 grid(Hv / 2, Dv, PH);
  warp_kernel<<<grid, 256>>>(mvf, (float4*)d_out);
}

// round 10
// speedup vs baseline: 1.0912x; 1.0912x over previous
#include <cuda_runtime.h>
#include <cuda_fp16.h>

// MVF_Dyn: trilinear-upsampled motion-field warp of a 2-channel 3D image.
//   image:       [1,1,48,256,256,2] f32
//   mvf_kernels: [1,4,3,48,128,128] f32
//   out:         [1,5,48,256,256,2] f32  (phase 0 = copy of image, 1..4 warped)
//
// Round-10: batched gathers. Sampler split into address/weight setup (OOB ->
// zero weights on clamped indices) and combine, so all 4 LDG.128s of a
// thread's 2 samples issue back-to-back with no intervening control flow
// (closes the 16% L1 idle gap of r9). Streaming stores (__stcs) for output
// so the write stream stops evicting the L2-resident g_pairs.

namespace {

constexpr int Dv = 48, Hv = 256, Wv = 256;
constexpr int HM = 128, WM = 128;
constexpr int PH = 4;

// 48*256*256 * 16B = 50.3 MB scratch (z+x paired fp16).
__device__ uint4 g_pairs[Dv * Hv * Wv];

__device__ __forceinline__ unsigned pack_h2(float a, float b) {
  __half2 h = __floats2half2_rn(a, b);
  return *reinterpret_cast<unsigned*>(&h);
}

// Builds g_pairs (fp16, z+x paired) and writes the phase-0 fp32 copy.
// Block = one (z,y) row; 128 threads, thread t owns pixels x = 2t, 2t+1.
__global__ void __launch_bounds__(128)
prep_kernel(const float4* __restrict__ img4, float4* __restrict__ out04) {
  const int y = blockIdx.x & (Hv - 1);
  const int z = blockIdx.x >> 8;       // Hv = 256
  const int t = threadIdx.x;           // 0..127 -> x-pair
  __shared__ float4 srow[2][WM + 1];   // [zrow][x-pair], +1 zero pad

  const int rbase4 = (z * Hv + y) * (Wv / 2);   // float4 units (2 px each)
  const float4 v0 = img4[rbase4 + t];           // px (2t, 2t+1) @ z
  float4 v1 = make_float4(0.f, 0.f, 0.f, 0.f);
  if (z + 1 < Dv) v1 = img4[rbase4 + Hv * (Wv / 2) + t];
  srow[0][t] = v0;
  srow[1][t] = v1;
  if (t == 0) {
    srow[0][WM] = make_float4(0.f, 0.f, 0.f, 0.f);
    srow[1][WM] = make_float4(0.f, 0.f, 0.f, 0.f);
  }
  __syncthreads();
  const float4 n0 = srow[0][t + 1];    // px (2t+2, 2t+3) @ z
  const float4 n1 = srow[1][t + 1];

  uint4 qa;  // entry x=2t:   (z,2t)(z,2t+1)(z+1,2t)(z+1,2t+1)
  qa.x = pack_h2(v0.x, v0.y);
  qa.y = pack_h2(v0.z, v0.w);
  qa.z = pack_h2(v1.x, v1.y);
  qa.w = pack_h2(v1.z, v1.w);
  uint4 qb;  // entry x=2t+1: (z,2t+1)(z,2t+2)(z+1,2t+1)(z+1,2t+2)
  qb.x = qa.y;
  qb.y = pack_h2(n0.x, n0.y);
  qb.z = qa.w;
  qb.w = pack_h2(n1.x, n1.y);

  const int ebase = (z * Hv + y) * Wv + 2 * t;
  g_pairs[ebase] = qa;
  g_pairs[ebase + 1] = qb;
  __stcs(&out04[rbase4 + t], v0);      // phase-0 copy, streaming
}

__device__ __forceinline__ float2 h2f(unsigned u) {
  return __half22float2(*reinterpret_cast<__half2*>(&u));
}

// Address + weight setup for one trilinear sample (zero-padding semantics).
// OOB taps -> zero weight on clamped (always-valid) indices; no branches.
struct Ctx {
  int i0, i1;                       // gather indices, rows y0 / y0+1
  float wa, wb, za, zb, wy0, wy1;   // x-half, z-half, y-row weights
};

__device__ __forceinline__ Ctx make_ctx(float z, float y, float x) {
  Ctx c;
  const int z0 = __float2int_rd(z);
  const int y0 = __float2int_rd(y);
  const int x0 = __float2int_rd(x);
  const float wz = z - (float)z0, wy = y - (float)y0, wx = x - (float)x0;

  const bool xin = (unsigned)x0 < (unsigned)Wv;
  const int xc = xin ? x0 : 0;
  c.wa = xin ? (1.f - wx) : ((x0 == -1) ? wx : 0.f);  // x0 half
  c.wb = xin ? wx : 0.f;                              // x0+1 half

  const bool zin = (unsigned)z0 < (unsigned)Dv;
  const int zc = zin ? z0 : 0;
  c.za = zin ? (1.f - wz) : ((z0 == -1) ? wz : 0.f);  // z lo half
  c.zb = zin ? wz : 0.f;                              // z hi half

  const int y0c = min(max(y0, 0), Hv - 1);
  const int y1c = min(max(y0 + 1, 0), Hv - 1);
  c.wy0 = ((unsigned)y0 < (unsigned)Hv) ? (1.f - wy) : 0.f;
  c.wy1 = ((unsigned)(y0 + 1) < (unsigned)Hv) ? wy : 0.f;

  const int base = zc * (Hv * Wv) + xc;               // 32-bit index
  c.i0 = base + y0c * Wv;
  c.i1 = base + y1c * Wv;
  return c;
}

__device__ __forceinline__ float2 combine(const Ctx& c, uint4 qa, uint4 qb) {
  float2 r;
  {
    const float2 a0 = h2f(qa.x), a1 = h2f(qa.y), b0 = h2f(qa.z), b1 = h2f(qa.w);
    const float t0x = fmaf(c.za, a0.x, c.zb * b0.x), t0y = fmaf(c.za, a0.y, c.zb * b0.y);
    const float t1x = fmaf(c.za, a1.x, c.zb * b1.x), t1y = fmaf(c.za, a1.y, c.zb * b1.y);
    r.x = c.wy0 * fmaf(c.wa, t0x, c.wb * t1x);
    r.y = c.wy0 * fmaf(c.wa, t0y, c.wb * t1y);
  }
  {
    const float2 a0 = h2f(qb.x), a1 = h2f(qb.y), b0 = h2f(qb.z), b1 = h2f(qb.w);
    const float t0x = fmaf(c.za, a0.x, c.zb * b0.x), t0y = fmaf(c.za, a0.y, c.zb * b0.y);
    const float t1x = fmaf(c.za, a1.x, c.zb * b1.x), t1y = fmaf(c.za, a1.y, c.zb * b1.y);
    r.x = fmaf(c.wy1, fmaf(c.wa, t0x, c.wb * t1x), r.x);
    r.y = fmaf(c.wy1, fmaf(c.wa, t0y, c.wb * t1y), r.y);
  }
  return r;
}

// Block: 256 threads = 2 output rows (h0, h0+1) of one (d, p).
// Thread: r = tid>>7 (row), k = tid&127 (w-pair) -> 2 samples, 4 LDG.128s
// issued back-to-back.
// jax.image.resize 'trilinear' 2x (half-pixel, edge-renormalized):
//   even out idx 2j   -> taps (j-1, j)  weights (0.25, 0.75), clamp at edges
//   odd  out idx 2j+1 -> taps (j, j+1)  weights (0.75, 0.25), clamp at edges
// Depth is identity.
__global__ void __launch_bounds__(256)
warp_kernel(const float* __restrict__ mvf,    // [4][3][48][128][128]
            float4* __restrict__ out) {       // output as float4 (w pairs)
  const int h0 = blockIdx.x * 2;
  const int d = blockIdx.y;
  const int p = blockIdx.z;
  const int tid = threadIdx.x;
  const int k = tid & (WM - 1);   // 0..127 w-pair
  const int r = tid >> 7;         // 0..1 output row
  const int a = h0 >> 1;

  // Stage mvf source rows a-1, a, a+1 (clamped) for 3 channels.
  __shared__ float s[3][3][WM];
  if (tid < WM) {
    const int r0 = max(a - 1, 0), r1 = a, r2 = min(a + 1, HM - 1);
    const float* pl = mvf + ((size_t)(p * 3) * Dv + d) * (size_t)(HM * WM);
    const int plane = Dv * HM * WM;
#pragma unroll
    for (int c = 0; c < 3; c++) {
      const float* pc = pl + c * plane;
      s[c][0][tid] = __ldg(pc + r0 * WM + tid);
      s[c][1][tid] = __ldg(pc + r1 * WM + tid);
      s[c][2][tid] = __ldg(pc + r2 * WM + tid);
    }
  }
  __syncthreads();

  const int km1 = max(k - 1, 0);
  const int kp1 = min(k + 1, WM - 1);

  // Row r: even row h0 uses y-taps (row0,row1) w/ (0.25,0.75);
  //        odd row h0+1 uses (row1,row2) w/ (0.75,0.25).
  const int ra = r ? 1 : 0, rb = r ? 2 : 1;
  const float tya = r ? 0.75f : 0.25f, tyb = r ? 0.25f : 0.75f;

  float me[3], mo[3];  // upsampled mvf at w=2k (even) and 2k+1 (odd)
#pragma unroll
  for (int c = 0; c < 3; c++) {
    const float aA = s[c][ra][km1], bA = s[c][ra][k], cA = s[c][ra][kp1];
    const float aB = s[c][rb][km1], bB = s[c][rb][k], cB = s[c][rb][kp1];
    const float eA = fmaf(0.25f, aA, 0.75f * bA), oA = fmaf(0.75f, bA, 0.25f * cA);
    const float eB = fmaf(0.25f, aB, 0.75f * bB), oB = fmaf(0.75f, bB, 0.25f * cB);
    me[c] = fmaf(tya, eA, tyb * eB);
    mo[c] = fmaf(tya, oA, tyb * oB);
  }

  const float fd = (float)d;
  const float fh = (float)(h0 + r);
  const float xe = (float)(2 * k), xo = (float)(2 * k + 1);

  const Ctx ce = make_ctx(fd + me[0], fh + 2.f * me[1], xe + 2.f * me[2]);
  const Ctx co = make_ctx(fd + mo[0], fh + 2.f * mo[1], xo + 2.f * mo[2]);

  // All four gathers in flight before any consumption.
  const uint4 qe0 = __ldg(&g_pairs[ce.i0]);
  const uint4 qe1 = __ldg(&g_pairs[ce.i1]);
  const uint4 qo0 = __ldg(&g_pairs[co.i0]);
  const uint4 qo1 = __ldg(&g_pairs[co.i1]);

  const float2 re = combine(ce, qe0, qe1);
  const float2 ro = combine(co, qo0, qo1);

  // 32-bit output index: max (5*48*256)*128 = 7.9M < 2^31.
  const int oidx = (((p + 1) * Dv + d) * Hv + (h0 + r)) * (Wv / 2) + k;
  __stcs(&out[oidx], make_float4(re.x, re.y, ro.x, ro.y));  // streaming store
}

}  // namespace

extern "C" void kernel_launch(void* const* d_in, const int* in_sizes, int n_in,
                              void* d_out, int out_size) {
  const float* image = (const float*)d_in[0];
  const float* mvf   = (const float*)d_in[1];
  // Defensive: identify inputs by size (image has 48*256*256*2 = 6291456 elems).
  if (n_in >= 2 && in_sizes[0] != Dv * Hv * Wv * 2) {
    const float* t = image; image = mvf; mvf = t;
  }

  // Build z+x paired fp16 layout + phase-0 copy (vectorized).
  prep_kernel<<<Dv * Hv, 128>>>((const float4*)image, (float4*)d_out);

  // Phases 1..4: warp. 2 output rows per 256-thread block.
  dim3 grid(Hv / 2, Dv, PH);
  warp_kernel<<<grid, 256>>>(mvf, (float4*)d_out);
}

// round 11
// speedup vs baseline: 1.1541x; 1.0577x over previous
#include <cuda_runtime.h>
#include <cuda_fp16.h>

// MVF_Dyn: trilinear-upsampled motion-field warp of a 2-channel 3D image.
//   image:       [1,1,48,256,256,2] f32
//   mvf_kernels: [1,4,3,48,128,128] f32
//   out:         [1,5,48,256,256,2] f32  (phase 0 = copy of image, 1..4 warped)
//
// Round-11: 4 samples per thread with round-10 economics. Thread k owns the
// w-pair k of BOTH output rows (h0, h0+1): 4 branch-free Ctx setups, then all
// 8 LDG.128s issued back-to-back (double the in-flight MLP of r10), then 4
// combines and 2 stores. Staging/store overhead amortized over 4 samples.

namespace {

constexpr int Dv = 48, Hv = 256, Wv = 256;
constexpr int HM = 128, WM = 128;
constexpr int PH = 4;

// 48*256*256 * 16B = 50.3 MB scratch (z+x paired fp16).
__device__ uint4 g_pairs[Dv * Hv * Wv];

__device__ __forceinline__ unsigned pack_h2(float a, float b) {
  __half2 h = __floats2half2_rn(a, b);
  return *reinterpret_cast<unsigned*>(&h);
}

// Builds g_pairs (fp16, z+x paired) and writes the phase-0 fp32 copy.
// Block = one (z,y) row; 128 threads, thread t owns pixels x = 2t, 2t+1.
__global__ void __launch_bounds__(128)
prep_kernel(const float4* __restrict__ img4, float4* __restrict__ out04) {
  const int y = blockIdx.x & (Hv - 1);
  const int z = blockIdx.x >> 8;       // Hv = 256
  const int t = threadIdx.x;           // 0..127 -> x-pair
  __shared__ float4 srow[2][WM + 1];   // [zrow][x-pair], +1 zero pad

  const int rbase4 = (z * Hv + y) * (Wv / 2);   // float4 units (2 px each)
  const float4 v0 = img4[rbase4 + t];           // px (2t, 2t+1) @ z
  float4 v1 = make_float4(0.f, 0.f, 0.f, 0.f);
  if (z + 1 < Dv) v1 = img4[rbase4 + Hv * (Wv / 2) + t];
  srow[0][t] = v0;
  srow[1][t] = v1;
  if (t == 0) {
    srow[0][WM] = make_float4(0.f, 0.f, 0.f, 0.f);
    srow[1][WM] = make_float4(0.f, 0.f, 0.f, 0.f);
  }
  __syncthreads();
  const float4 n0 = srow[0][t + 1];    // px (2t+2, 2t+3) @ z
  const float4 n1 = srow[1][t + 1];

  uint4 qa;  // entry x=2t:   (z,2t)(z,2t+1)(z+1,2t)(z+1,2t+1)
  qa.x = pack_h2(v0.x, v0.y);
  qa.y = pack_h2(v0.z, v0.w);
  qa.z = pack_h2(v1.x, v1.y);
  qa.w = pack_h2(v1.z, v1.w);
  uint4 qb;  // entry x=2t+1: (z,2t+1)(z,2t+2)(z+1,2t+1)(z+1,2t+2)
  qb.x = qa.y;
  qb.y = pack_h2(n0.x, n0.y);
  qb.z = qa.w;
  qb.w = pack_h2(n1.x, n1.y);

  const int ebase = (z * Hv + y) * Wv + 2 * t;
  g_pairs[ebase] = qa;
  g_pairs[ebase + 1] = qb;
  __stcs(&out04[rbase4 + t], v0);      // phase-0 copy, streaming
}

__device__ __forceinline__ float2 h2f(unsigned u) {
  return __half22float2(*reinterpret_cast<__half2*>(&u));
}

// Address + weight setup for one trilinear sample (zero-padding semantics).
// OOB taps -> zero weight on clamped (always-valid) indices; no branches.
struct Ctx {
  int i0, i1;                       // gather indices, rows y0 / y0+1
  float wa, wb, za, zb, wy0, wy1;   // x-half, z-half, y-row weights
};

__device__ __forceinline__ Ctx make_ctx(float z, float y, float x) {
  Ctx c;
  const int z0 = __float2int_rd(z);
  const int y0 = __float2int_rd(y);
  const int x0 = __float2int_rd(x);
  const float wz = z - (float)z0, wy = y - (float)y0, wx = x - (float)x0;

  const bool xin = (unsigned)x0 < (unsigned)Wv;
  const int xc = xin ? x0 : 0;
  c.wa = xin ? (1.f - wx) : ((x0 == -1) ? wx : 0.f);  // x0 half
  c.wb = xin ? wx : 0.f;                              // x0+1 half

  const bool zin = (unsigned)z0 < (unsigned)Dv;
  const int zc = zin ? z0 : 0;
  c.za = zin ? (1.f - wz) : ((z0 == -1) ? wz : 0.f);  // z lo half
  c.zb = zin ? wz : 0.f;                              // z hi half

  const int y0c = min(max(y0, 0), Hv - 1);
  const int y1c = min(max(y0 + 1, 0), Hv - 1);
  c.wy0 = ((unsigned)y0 < (unsigned)Hv) ? (1.f - wy) : 0.f;
  c.wy1 = ((unsigned)(y0 + 1) < (unsigned)Hv) ? wy : 0.f;

  const int base = zc * (Hv * Wv) + xc;               // 32-bit index
  c.i0 = base + y0c * Wv;
  c.i1 = base + y1c * Wv;
  return c;
}

__device__ __forceinline__ float2 combine(const Ctx& c, uint4 qa, uint4 qb) {
  float2 r;
  {
    const float2 a0 = h2f(qa.x), a1 = h2f(qa.y), b0 = h2f(qa.z), b1 = h2f(qa.w);
    const float t0x = fmaf(c.za, a0.x, c.zb * b0.x), t0y = fmaf(c.za, a0.y, c.zb * b0.y);
    const float t1x = fmaf(c.za, a1.x, c.zb * b1.x), t1y = fmaf(c.za, a1.y, c.zb * b1.y);
    r.x = c.wy0 * fmaf(c.wa, t0x, c.wb * t1x);
    r.y = c.wy0 * fmaf(c.wa, t0y, c.wb * t1y);
  }
  {
    const float2 a0 = h2f(qb.x), a1 = h2f(qb.y), b0 = h2f(qb.z), b1 = h2f(qb.w);
    const float t0x = fmaf(c.za, a0.x, c.zb * b0.x), t0y = fmaf(c.za, a0.y, c.zb * b0.y);
    const float t1x = fmaf(c.za, a1.x, c.zb * b1.x), t1y = fmaf(c.za, a1.y, c.zb * b1.y);
    r.x = fmaf(c.wy1, fmaf(c.wa, t0x, c.wb * t1x), r.x);
    r.y = fmaf(c.wy1, fmaf(c.wa, t0y, c.wb * t1y), r.y);
  }
  return r;
}

// Block: 128 threads = 2 output rows (h0, h0+1) of one (d, p).
// Thread k owns w-pair k on BOTH rows: 4 samples, 8 LDG.128s batched.
// jax.image.resize 'trilinear' 2x (half-pixel, edge-renormalized):
//   even out idx 2j   -> taps (j-1, j)  weights (0.25, 0.75), clamp at edges
//   odd  out idx 2j+1 -> taps (j, j+1)  weights (0.75, 0.25), clamp at edges
// Depth is identity.
__global__ void __launch_bounds__(128, 8)
warp_kernel(const float* __restrict__ mvf,    // [4][3][48][128][128]
            float4* __restrict__ out) {       // output as float4 (w pairs)
  const int h0 = blockIdx.x * 2;
  const int d = blockIdx.y;
  const int p = blockIdx.z;
  const int k = threadIdx.x;      // 0..127 w-pair
  const int a = h0 >> 1;

  // Stage mvf source rows a-1, a, a+1 (clamped) for 3 channels.
  __shared__ float s[3][3][WM];
  {
    const int r0 = max(a - 1, 0), r1 = a, r2 = min(a + 1, HM - 1);
    const float* pl = mvf + ((size_t)(p * 3) * Dv + d) * (size_t)(HM * WM);
    const int plane = Dv * HM * WM;
#pragma unroll
    for (int c = 0; c < 3; c++) {
      const float* pc = pl + c * plane;
      s[c][0][k] = __ldg(pc + r0 * WM + k);
      s[c][1][k] = __ldg(pc + r1 * WM + k);
      s[c][2][k] = __ldg(pc + r2 * WM + k);
    }
  }
  __syncthreads();

  const int km1 = max(k - 1, 0);
  const int kp1 = min(k + 1, WM - 1);

  // mvf upsampled at (row h0 even/odd w) and (row h0+1 even/odd w).
  // row h0   (even h): y-taps (r0,r1) weights (0.25, 0.75)
  // row h0+1 (odd  h): y-taps (r1,r2) weights (0.75, 0.25)
  float mA[3], mB[3], mC[3], mD[3];
#pragma unroll
  for (int c = 0; c < 3; c++) {
    const float a0 = s[c][0][km1], b0 = s[c][0][k], c0 = s[c][0][kp1];
    const float a1 = s[c][1][km1], b1 = s[c][1][k], c1 = s[c][1][kp1];
    const float a2 = s[c][2][km1], b2 = s[c][2][k], c2 = s[c][2][kp1];
    const float e0 = fmaf(0.25f, a0, 0.75f * b0), o0 = fmaf(0.75f, b0, 0.25f * c0);
    const float e1 = fmaf(0.25f, a1, 0.75f * b1), o1 = fmaf(0.75f, b1, 0.25f * c1);
    const float e2 = fmaf(0.25f, a2, 0.75f * b2), o2 = fmaf(0.75f, b2, 0.25f * c2);
    mA[c] = fmaf(0.25f, e0, 0.75f * e1);  // row h0,   even w
    mB[c] = fmaf(0.25f, o0, 0.75f * o1);  // row h0,   odd  w
    mC[c] = fmaf(0.75f, e1, 0.25f * e2);  // row h0+1, even w
    mD[c] = fmaf(0.75f, o1, 0.25f * o2);  // row h0+1, odd  w
  }

  const float fd = (float)d;
  const float f0 = (float)h0, f1 = (float)(h0 + 1);
  const float xe = (float)(2 * k), xo = (float)(2 * k + 1);

  const Ctx cA = make_ctx(fd + mA[0], f0 + 2.f * mA[1], xe + 2.f * mA[2]);
  const Ctx cB = make_ctx(fd + mB[0], f0 + 2.f * mB[1], xo + 2.f * mB[2]);
  const Ctx cC = make_ctx(fd + mC[0], f1 + 2.f * mC[1], xe + 2.f * mC[2]);
  const Ctx cD = make_ctx(fd + mD[0], f1 + 2.f * mD[1], xo + 2.f * mD[2]);

  // All eight gathers in flight before any consumption.
  const uint4 qA0 = __ldg(&g_pairs[cA.i0]);
  const uint4 qA1 = __ldg(&g_pairs[cA.i1]);
  const uint4 qB0 = __ldg(&g_pairs[cB.i0]);
  const uint4 qB1 = __ldg(&g_pairs[cB.i1]);
  const uint4 qC0 = __ldg(&g_pairs[cC.i0]);
  const uint4 qC1 = __ldg(&g_pairs[cC.i1]);
  const uint4 qD0 = __ldg(&g_pairs[cD.i0]);
  const uint4 qD1 = __ldg(&g_pairs[cD.i1]);

  const float2 rA = combine(cA, qA0, qA1);
  const float2 rB = combine(cB, qB0, qB1);
  const float2 rC = combine(cC, qC0, qC1);
  const float2 rD = combine(cD, qD0, qD1);

  // 32-bit output index: max (5*48*256)*128 = 7.9M < 2^31.
  const int oidx = (((p + 1) * Dv + d) * Hv + h0) * (Wv / 2) + k;
  __stcs(&out[oidx], make_float4(rA.x, rA.y, rB.x, rB.y));
  __stcs(&out[oidx + (Wv / 2)], make_float4(rC.x, rC.y, rD.x, rD.y));
}

}  // namespace

extern "C" void kernel_launch(void* const* d_in, const int* in_sizes, int n_in,
                              void* d_out, int out_size) {
  const float* image = (const float*)d_in[0];
  const float* mvf   = (const float*)d_in[1];
  // Defensive: identify inputs by size (image has 48*256*256*2 = 6291456 elems).
  if (n_in >= 2 && in_sizes[0] != Dv * Hv * Wv * 2) {
    const float* t = image; image = mvf; mvf = t;
  }

  // Build z+x paired fp16 layout + phase-0 copy (vectorized).
  prep_kernel<<<Dv * Hv, 128>>>((const float4*)image, (float4*)d_out);

  // Phases 1..4: warp. 2 output rows per 128-thread block, 4 samples/thread.
  dim3 grid(Hv / 2, Dv, PH);
  warp_kernel<<<grid, 128>>>(mvf, (float4*)d_out);
}